// round 7
// baseline (speedup 1.0000x reference)
#include <cuda_runtime.h>
#include <math.h>

// Problem constants
#define Bsz   32
#define Tn    512
#define Jn    25
#define DENC  256
#define Hn    512
#define G4    2048      // 4*H
#define NB    64        // persistent recurrence grid (co-resident)

// ---------------- scratch (device globals; no allocations) ----------------
__device__ float    g_enc [Bsz * Tn * DENC];
__device__ float    g_xg  [2L * Tn * Bsz * G4];           // [d][t][b][4H]
__device__ float    g_out0[Bsz * Tn * 2 * Hn];            // [b][t][2H]
__device__ float    g_out1[Bsz * Tn * 2 * Hn];
__device__ unsigned g_h   [2][2 * Bsz * Hn];              // tf32 bits, double-buffered
__device__ unsigned g_bar_cnt;
__device__ unsigned g_bar_gen;

// ---------------- helpers --------------------------------------------------
__device__ __forceinline__ unsigned f2tf(float x) {
    unsigned u;
    asm("cvt.rna.tf32.f32 %0, %1;" : "=r"(u) : "f"(x));
    return u;
}

__device__ __forceinline__ void mma_tf32(float* c,
                                         unsigned a0, unsigned a1,
                                         unsigned a2, unsigned a3,
                                         unsigned b0, unsigned b1) {
    asm("mma.sync.aligned.m16n8k8.row.col.f32.tf32.tf32.f32 "
        "{%0,%1,%2,%3}, {%4,%5,%6,%7}, {%8,%9}, {%0,%1,%2,%3};"
        : "+f"(c[0]), "+f"(c[1]), "+f"(c[2]), "+f"(c[3])
        : "r"(a0), "r"(a1), "r"(a2), "r"(a3), "r"(b0), "r"(b1));
}

// ---------------- grid-wide barrier (all NB blocks resident) --------------
__device__ __forceinline__ void grid_sync() {
    __threadfence();
    __syncthreads();
    if (threadIdx.x == 0) {
        volatile unsigned* vg = &g_bar_gen;
        unsigned gen = *vg;
        if (atomicAdd(&g_bar_cnt, 1u) == NB - 1) {
            g_bar_cnt = 0;
            __threadfence();
            *vg = gen + 1;
        } else {
            while (*vg == gen) { __nanosleep(32); }
        }
    }
    __syncthreads();
    __threadfence();
}

// ---------------- zero the output buffers ---------------------------------
__global__ void zero_kernel() {
    const int n4 = (Bsz * Tn * 2 * Hn) / 4;
    float4 z = make_float4(0.f, 0.f, 0.f, 0.f);
    for (int i = blockIdx.x * blockDim.x + threadIdx.x; i < n4;
         i += gridDim.x * blockDim.x) {
        reinterpret_cast<float4*>(g_out0)[i] = z;
        reinterpret_cast<float4*>(g_out1)[i] = z;
    }
}

// ---------------- encoder: relu(masked_xy @ W^T + b) ----------------------
__global__ void enc_kernel(const float* __restrict__ feats,
                           const float* __restrict__ W,
                           const float* __restrict__ bias) {
    __shared__ float xs[2 * Jn];
    const int bt  = blockIdx.x;
    const int tid = threadIdx.x;
    const float* f = feats + (size_t)bt * (Jn * 3);
    if (tid < Jn) {
        float c = (f[tid * 3 + 2] > 0.1f) ? 1.f : 0.f;
        xs[tid * 2 + 0] = f[tid * 3 + 0] * c;
        xs[tid * 2 + 1] = f[tid * 3 + 1] * c;
    }
    __syncthreads();
    const float* w = W + tid * (2 * Jn);
    float s = bias[tid];
#pragma unroll
    for (int k = 0; k < 2 * Jn; ++k) s += xs[k] * w[k];
    g_enc[(size_t)bt * DENC + tid] = fmaxf(s, 0.f);
}

// ---------------- input projection GEMM (tf32, ping-pong k-tile 32) -------
// out_xg[d][t][b][g] = A[m=b*T+t,:K] . W[d][g,:K] + bias[d][g]
// block 128x128, 8 warps (2m x 4n), warp 64x32
#define PROJ_SMEM (4 * 128 * 36 * 4)
extern __shared__ unsigned smp[];

__global__ void __launch_bounds__(256)
proj_gemm(int srcSel, int K, const float* __restrict__ W,
          const float* __restrict__ bias) {
    const float* A  = srcSel ? g_out0 : g_enc;
    const int d  = blockIdx.z;
    const float* Wd = W + (size_t)d * G4 * K;
    const float* bd = bias + d * G4;
    const int n0 = blockIdx.x * 128;
    const int m0 = blockIdx.y * 128;

    unsigned* As = smp;                   // [2][128*36]
    unsigned* Bs = smp + 2 * 128 * 36;

    const int tid  = threadIdx.x;
    const int lane = tid & 31;
    const int wid  = tid >> 5;
    const int wm   = (wid >> 2) * 64;
    const int wn   = (wid & 3) * 32;

    float acc[4][4][4];
#pragma unroll
    for (int mt = 0; mt < 4; ++mt)
#pragma unroll
        for (int nt = 0; nt < 4; ++nt)
#pragma unroll
            for (int i = 0; i < 4; ++i) acc[mt][nt][i] = 0.f;

    float4 ra[4], rw[4];
#pragma unroll
    for (int j = 0; j < 4; ++j) {
        int u = tid + j * 256, r = u >> 3, kq = (u & 7) << 2;
        ra[j] = *reinterpret_cast<const float4*>(A  + (size_t)(m0 + r) * K + kq);
        rw[j] = *reinterpret_cast<const float4*>(Wd + (size_t)(n0 + r) * K + kq);
    }

    const int KT = K >> 5;
    for (int kt = 0; kt < KT; ++kt) {
        const int p = kt & 1;
        // convert + store staged tile into buffer p
#pragma unroll
        for (int j = 0; j < 4; ++j) {
            int u = tid + j * 256, r = u >> 3, kq = (u & 7) << 2;
            uint4 ua, uw;
            ua.x = f2tf(ra[j].x); ua.y = f2tf(ra[j].y);
            ua.z = f2tf(ra[j].z); ua.w = f2tf(ra[j].w);
            uw.x = f2tf(rw[j].x); uw.y = f2tf(rw[j].y);
            uw.z = f2tf(rw[j].z); uw.w = f2tf(rw[j].w);
            *reinterpret_cast<uint4*>(As + p * 4608 + r * 36 + kq) = ua;
            *reinterpret_cast<uint4*>(Bs + p * 4608 + r * 36 + kq) = uw;
        }
        __syncthreads();

        if (kt + 1 < KT) {   // prefetch next tile
            int kb = (kt + 1) * 32;
#pragma unroll
            for (int j = 0; j < 4; ++j) {
                int u = tid + j * 256, r = u >> 3, kq = (u & 7) << 2;
                ra[j] = *reinterpret_cast<const float4*>(A  + (size_t)(m0 + r) * K + kb + kq);
                rw[j] = *reinterpret_cast<const float4*>(Wd + (size_t)(n0 + r) * K + kb + kq);
            }
        }

        const unsigned* Ab = As + p * 4608;
        const unsigned* Bb = Bs + p * 4608;
#pragma unroll
        for (int kk = 0; kk < 32; kk += 8) {
            unsigned af[4][4], bf[4][2];
#pragma unroll
            for (int mt = 0; mt < 4; ++mt) {
                const unsigned* pp = Ab + (wm + mt * 16 + (lane >> 2)) * 36 + kk + (lane & 3);
                af[mt][0] = pp[0];
                af[mt][1] = pp[8 * 36];
                af[mt][2] = pp[4];
                af[mt][3] = pp[8 * 36 + 4];
            }
#pragma unroll
            for (int nt = 0; nt < 4; ++nt) {
                const unsigned* pp = Bb + (wn + nt * 8 + (lane >> 2)) * 36 + kk + (lane & 3);
                bf[nt][0] = pp[0];
                bf[nt][1] = pp[4];
            }
#pragma unroll
            for (int mt = 0; mt < 4; ++mt)
#pragma unroll
                for (int nt = 0; nt < 4; ++nt)
                    mma_tf32(acc[mt][nt], af[mt][0], af[mt][1], af[mt][2], af[mt][3],
                             bf[nt][0], bf[nt][1]);
        }
        __syncthreads();
    }

    // epilogue: bias + scatter to g_xg [d][t][b][g]
#pragma unroll
    for (int mt = 0; mt < 4; ++mt) {
        int mrow0 = m0 + wm + mt * 16 + (lane >> 2);
#pragma unroll
        for (int nt = 0; nt < 4; ++nt) {
            int n = n0 + wn + nt * 8 + (lane & 3) * 2;
            float bv0 = bd[n], bv1 = bd[n + 1];
#pragma unroll
            for (int h = 0; h < 2; ++h) {
                int m  = mrow0 + h * 8;
                int t  = m & (Tn - 1);
                int bb = m >> 9;
                float* cp = g_xg + (((size_t)d * Tn + t) * Bsz + bb) * G4 + n;
                *reinterpret_cast<float2*>(cp) =
                    make_float2(acc[mt][nt][h * 2 + 0] + bv0,
                                acc[mt][nt][h * 2 + 1] + bv1);
            }
        }
    }
}

// ---------------- persistent bidirectional LSTM recurrence (tf32 MMA) -----
// NB=64 blocks: (d = bx>>5, j-slice j0 = (bx&31)*16 -> 64 gate rows).
// MMA: C[gate 64][batch 32] = W_slice[64,512] x h[32,512]^T, m16n8k8 tf32.
// A = W stationary in regs (8ks x 4q x 4 = 128 regs); 8-way K-split (warp=kc).
// Block-local partial reduction in smem; ONE grid_sync per step.
#define REC_SMEM ((32 * 520 + 8 * 64 * 34) * 4)
extern __shared__ unsigned smr[];

__global__ void __launch_bounds__(256, 1)
rec_kernel(const float* __restrict__ whh,      // [2][4H][H]
           const int*   __restrict__ lengths,
           int outSel) {
    unsigned* hs   = smr;                          // [32 b][520] (tf32 bits)
    float*    part = (float*)(smr + 32 * 520);     // [8 kc][64 g][34 b]
    float* out = outSel ? g_out1 : g_out0;

    const int tid  = threadIdx.x;
    const int lane = tid & 31;
    const int kc   = tid >> 5;            // warp id = K chunk (0..7)
    const int bx   = blockIdx.x;
    const int d    = bx >> 5;
    const int j0   = (bx & 31) << 4;

    // stationary W fragments (A side): wa[ks][q][0..3]
    unsigned wa[8][4][4];
    {
        const float* wdb = whh + (size_t)d * G4 * Hn;
#pragma unroll
        for (int ks = 0; ks < 8; ++ks)
#pragma unroll
            for (int q = 0; q < 4; ++q) {
                const float* wp = wdb + (size_t)(q * Hn + j0 + (lane >> 2)) * Hn
                                  + kc * 64 + ks * 8 + (lane & 3);
                wa[ks][q][0] = f2tf(wp[0]);
                wa[ks][q][1] = f2tf(wp[8 * (size_t)Hn]);
                wa[ks][q][2] = f2tf(wp[4]);
                wa[ks][q][3] = f2tf(wp[8 * (size_t)Hn + 4]);
            }
    }

    // phase-2 identity: jj-major lanes -> coalesced xg/out/h accesses
    const int jj  = tid & 15;
    const int b2a = tid >> 4;             // 0..15 ; second batch = b2a+16
    const int lenA = lengths[b2a];
    const int lenB = lengths[b2a + 16];
    const int hidxA = (d * Bsz + b2a) * Hn + j0 + jj;
    const int hidxB = hidxA + 16 * Hn;
    float cA = 0.f, cB = 0.f;
    unsigned hbA = 0u, hbB = 0u;
    g_h[0][hidxA] = 0u;
    g_h[0][hidxB] = 0u;

    grid_sync();   // h buffer 0 zeroed everywhere

    for (int s = 0; s < Tn; ++s) {
        const int pr = s & 1, pw_ = pr ^ 1;
        const bool actA = s < lenA, actB = s < lenB;
        const int tA = d ? (lenA - 1 - s) : s;
        const int tB = d ? (lenB - 1 - s) : s;

        // prefetch xg (coalesced 64B per (q,halfwarp))
        float xvA[4], xvB[4];
        if (actA) {
            const float* xr = g_xg + (((size_t)d * Tn + tA) * Bsz + b2a) * G4 + j0 + jj;
            xvA[0] = xr[0]; xvA[1] = xr[Hn]; xvA[2] = xr[2 * Hn]; xvA[3] = xr[3 * Hn];
        }
        if (actB) {
            const float* xr = g_xg + (((size_t)d * Tn + tB) * Bsz + b2a + 16) * G4 + j0 + jj;
            xvB[0] = xr[0]; xvB[1] = xr[Hn]; xvB[2] = xr[2 * Hn]; xvB[3] = xr[3 * Hn];
        }

        // stage h (own dir, 64KB) into smem [b][k], straight coalesced copy
        {
            const unsigned* hsrc = g_h[pr] + d * Bsz * Hn;
#pragma unroll
            for (int i = 0; i < 16; ++i) {
                int f = tid + i * 256;
                int r = f >> 7, kq = (f & 127) << 2;
                *reinterpret_cast<uint4*>(hs + r * 520 + kq) =
                    *reinterpret_cast<const uint4*>(hsrc + r * Hn + kq);
            }
        }
        __syncthreads();

        float acc[4][4][4];
#pragma unroll
        for (int q = 0; q < 4; ++q)
#pragma unroll
            for (int nt = 0; nt < 4; ++nt)
#pragma unroll
                for (int i = 0; i < 4; ++i) acc[q][nt][i] = 0.f;

#pragma unroll
        for (int ks = 0; ks < 8; ++ks) {
#pragma unroll
            for (int nt = 0; nt < 4; ++nt) {
                const unsigned* hp = hs + (nt * 8 + (lane >> 2)) * 520
                                     + kc * 64 + ks * 8 + (lane & 3);
                unsigned b0 = hp[0], b1 = hp[4];
#pragma unroll
                for (int q = 0; q < 4; ++q)
                    mma_tf32(acc[q][nt], wa[ks][q][0], wa[ks][q][1],
                             wa[ks][q][2], wa[ks][q][3], b0, b1);
            }
        }

        // write K-chunk partials: part[kc][gate row][batch]
#pragma unroll
        for (int q = 0; q < 4; ++q)
#pragma unroll
            for (int nt = 0; nt < 4; ++nt) {
                float* pp = part + ((size_t)kc * 64 + q * 16 + (lane >> 2)) * 34
                            + nt * 8 + ((lane & 3) << 1);
                *reinterpret_cast<float2*>(pp) =
                    make_float2(acc[q][nt][0], acc[q][nt][1]);
                *reinterpret_cast<float2*>(pp + 8 * 34) =
                    make_float2(acc[q][nt][2], acc[q][nt][3]);
            }
        __syncthreads();

        // phase 2: reduce partials + gates (2 batches per thread)
        if (actA) {
            float gv[4];
#pragma unroll
            for (int q = 0; q < 4; ++q) {
                float v = xvA[q];
#pragma unroll
                for (int k2 = 0; k2 < 8; ++k2)
                    v += part[(k2 * 64 + q * 16 + jj) * 34 + b2a];
                gv[q] = v;
            }
            float ig = 1.f / (1.f + __expf(-gv[0]));
            float fg = 1.f / (1.f + __expf(-gv[1]));
            float gg = tanhf(gv[2]);
            float og = 1.f / (1.f + __expf(-gv[3]));
            cA = fg * cA + ig * gg;
            float hn = og * tanhf(cA);
            hbA = f2tf(hn);
            out[((size_t)b2a * Tn + tA) * (2 * Hn) + d * Hn + j0 + jj] = hn;
        }
        if (actB) {
            float gv[4];
#pragma unroll
            for (int q = 0; q < 4; ++q) {
                float v = xvB[q];
#pragma unroll
                for (int k2 = 0; k2 < 8; ++k2)
                    v += part[(k2 * 64 + q * 16 + jj) * 34 + b2a + 16];
                gv[q] = v;
            }
            float ig = 1.f / (1.f + __expf(-gv[0]));
            float fg = 1.f / (1.f + __expf(-gv[1]));
            float gg = tanhf(gv[2]);
            float og = 1.f / (1.f + __expf(-gv[3]));
            cB = fg * cB + ig * gg;
            float hn = og * tanhf(cB);
            hbB = f2tf(hn);
            out[((size_t)(b2a + 16) * Tn + tB) * (2 * Hn) + d * Hn + j0 + jj] = hn;
        }
        g_h[pw_][hidxA] = hbA;   // frozen h re-written when inactive
        g_h[pw_][hidxB] = hbB;

        grid_sync();
    }
}

// ---------------- mean pooling over valid length --------------------------
__global__ void pool_kernel(const int* __restrict__ lengths,
                            float* __restrict__ out) {
    const int c = blockIdx.x * 256 + threadIdx.x;
    const int b = blockIdx.y;
    const float* p = g_out1 + (size_t)b * Tn * (2 * Hn) + c;
    float s = 0.f;
    for (int t = 0; t < Tn; ++t) s += p[(size_t)t * (2 * Hn)];
    out[b * (2 * Hn) + c] = s / (float)lengths[b];
}

// ---------------- launch ---------------------------------------------------
extern "C" void kernel_launch(void* const* d_in, const int* in_sizes, int n_in,
                              void* d_out, int out_size) {
    const float* feats = (const float*)d_in[0];
    const int*   lens  = (const int*)  d_in[1];
    const float* encW  = (const float*)d_in[2];
    const float* encb  = (const float*)d_in[3];
    const float* wih0  = (const float*)d_in[4];
    const float* whh0  = (const float*)d_in[5];
    const float* b0    = (const float*)d_in[6];
    const float* wih1  = (const float*)d_in[7];
    const float* whh1  = (const float*)d_in[8];
    const float* b1    = (const float*)d_in[9];
    float* out = (float*)d_out;

    // opt-in to >48KB dynamic smem (attribute set, not an allocation)
    cudaFuncSetAttribute(rec_kernel,
                         cudaFuncAttributeMaxDynamicSharedMemorySize, REC_SMEM);
    cudaFuncSetAttribute(proj_gemm,
                         cudaFuncAttributeMaxDynamicSharedMemorySize, PROJ_SMEM);

    zero_kernel<<<2048, 256>>>();
    enc_kernel<<<Bsz * Tn, 256>>>(feats, encW, encb);

    // layer 0: project (K=256) then scan
    {
        dim3 grid(16, 128, 2);
        proj_gemm<<<grid, 256, PROJ_SMEM>>>(0, DENC, wih0, b0);
        rec_kernel<<<NB, 256, REC_SMEM>>>(whh0, lens, 0);
    }
    // layer 1: project (K=1024) then scan
    {
        dim3 grid(16, 128, 2);
        proj_gemm<<<grid, 256, PROJ_SMEM>>>(1, 2 * Hn, wih1, b1);
        rec_kernel<<<NB, 256, REC_SMEM>>>(whh1, lens, 1);
    }

    dim3 pg(4, Bsz);
    pool_kernel<<<pg, 256>>>(lens, out);
}

// round 8
// speedup vs baseline: 1.0383x; 1.0383x over previous
#include <cuda_runtime.h>
#include <math.h>

// Problem constants
#define Bsz   32
#define Tn    512
#define Jn    25
#define DENC  256
#define Hn    512
#define G4    2048      // 4*H
#define NB    64        // persistent recurrence grid (co-resident)

// ---------------- scratch (device globals; no allocations) ----------------
__device__ float    g_enc [Bsz * Tn * DENC];
__device__ float    g_xg  [2L * Tn * Bsz * G4];           // [d][t][b][4H]
__device__ float    g_out0[Bsz * Tn * 2 * Hn];            // [b][t][2H]
__device__ float    g_out1[Bsz * Tn * 2 * Hn];
__device__ unsigned g_h   [2][2 * Bsz * Hn];              // tf32 bits, double-buffered
__device__ unsigned g_bar_cnt;
__device__ unsigned g_bar_gen;

// ---------------- helpers --------------------------------------------------
__device__ __forceinline__ unsigned f2tf(float x) {
    unsigned u;
    asm("cvt.rna.tf32.f32 %0, %1;" : "=r"(u) : "f"(x));
    return u;
}

__device__ __forceinline__ void mma_tf32(float* c,
                                         unsigned a0, unsigned a1,
                                         unsigned a2, unsigned a3,
                                         unsigned b0, unsigned b1) {
    asm("mma.sync.aligned.m16n8k8.row.col.f32.tf32.tf32.f32 "
        "{%0,%1,%2,%3}, {%4,%5,%6,%7}, {%8,%9}, {%0,%1,%2,%3};"
        : "+f"(c[0]), "+f"(c[1]), "+f"(c[2]), "+f"(c[3])
        : "r"(a0), "r"(a1), "r"(a2), "r"(a3), "r"(b0), "r"(b1));
}

// ---------------- grid-wide barrier (all NB blocks resident) --------------
__device__ __forceinline__ void grid_sync() {
    __threadfence();
    __syncthreads();
    if (threadIdx.x == 0) {
        volatile unsigned* vg = &g_bar_gen;
        unsigned gen = *vg;
        if (atomicAdd(&g_bar_cnt, 1u) == NB - 1) {
            g_bar_cnt = 0;
            __threadfence();
            *vg = gen + 1;
        } else {
            while (*vg == gen) { __nanosleep(32); }
        }
    }
    __syncthreads();
    __threadfence();
}

// ---------------- zero the output buffers ---------------------------------
__global__ void zero_kernel() {
    const int n4 = (Bsz * Tn * 2 * Hn) / 4;
    float4 z = make_float4(0.f, 0.f, 0.f, 0.f);
    for (int i = blockIdx.x * blockDim.x + threadIdx.x; i < n4;
         i += gridDim.x * blockDim.x) {
        reinterpret_cast<float4*>(g_out0)[i] = z;
        reinterpret_cast<float4*>(g_out1)[i] = z;
    }
}

// ---------------- encoder: relu(masked_xy @ W^T + b) ----------------------
__global__ void enc_kernel(const float* __restrict__ feats,
                           const float* __restrict__ W,
                           const float* __restrict__ bias) {
    __shared__ float xs[2 * Jn];
    const int bt  = blockIdx.x;
    const int tid = threadIdx.x;
    const float* f = feats + (size_t)bt * (Jn * 3);
    if (tid < Jn) {
        float c = (f[tid * 3 + 2] > 0.1f) ? 1.f : 0.f;
        xs[tid * 2 + 0] = f[tid * 3 + 0] * c;
        xs[tid * 2 + 1] = f[tid * 3 + 1] * c;
    }
    __syncthreads();
    const float* w = W + tid * (2 * Jn);
    float s = bias[tid];
#pragma unroll
    for (int k = 0; k < 2 * Jn; ++k) s += xs[k] * w[k];
    g_enc[(size_t)bt * DENC + tid] = fmaxf(s, 0.f);
}

// ---------------- input projection GEMM (tf32 tensor cores) ---------------
// R5 version (known good): block 128x128, 8 warps (2m x 4n), k-tile 16
__global__ void __launch_bounds__(256)
proj_gemm(int srcSel, int K, const float* __restrict__ W,
          const float* __restrict__ bias) {
    const float* A  = srcSel ? g_out0 : g_enc;
    const int d  = blockIdx.z;
    const float* Wd = W + (size_t)d * G4 * K;
    const float* bd = bias + d * G4;
    const int n0 = blockIdx.x * 128;
    const int m0 = blockIdx.y * 128;

    __shared__ unsigned As[128 * 20];   // [m][k], stride 20 -> conflict-free frags
    __shared__ unsigned Ws[128 * 20];   // [n][k]

    const int tid  = threadIdx.x;
    const int lane = tid & 31;
    const int wid  = tid >> 5;
    const int wm   = (wid >> 2) * 64;
    const int wn   = (wid & 3) * 32;

    float acc[4][4][4];
#pragma unroll
    for (int mt = 0; mt < 4; ++mt)
#pragma unroll
        for (int nt = 0; nt < 4; ++nt)
#pragma unroll
            for (int i = 0; i < 4; ++i) acc[mt][nt][i] = 0.f;

    const int r0  = tid >> 2;
    const int kq0 = (tid & 3) << 2;

    float4 pa0, pa1, pw0, pw1;
    pa0 = *reinterpret_cast<const float4*>(A  + (size_t)(m0 + r0)      * K + kq0);
    pa1 = *reinterpret_cast<const float4*>(A  + (size_t)(m0 + r0 + 64) * K + kq0);
    pw0 = *reinterpret_cast<const float4*>(Wd + (size_t)(n0 + r0)      * K + kq0);
    pw1 = *reinterpret_cast<const float4*>(Wd + (size_t)(n0 + r0 + 64) * K + kq0);

    for (int kt = 0; kt < K; kt += 16) {
        {
            uint4 u;
            u.x = f2tf(pa0.x); u.y = f2tf(pa0.y); u.z = f2tf(pa0.z); u.w = f2tf(pa0.w);
            *reinterpret_cast<uint4*>(As + r0 * 20 + kq0) = u;
            u.x = f2tf(pa1.x); u.y = f2tf(pa1.y); u.z = f2tf(pa1.z); u.w = f2tf(pa1.w);
            *reinterpret_cast<uint4*>(As + (r0 + 64) * 20 + kq0) = u;
            u.x = f2tf(pw0.x); u.y = f2tf(pw0.y); u.z = f2tf(pw0.z); u.w = f2tf(pw0.w);
            *reinterpret_cast<uint4*>(Ws + r0 * 20 + kq0) = u;
            u.x = f2tf(pw1.x); u.y = f2tf(pw1.y); u.z = f2tf(pw1.z); u.w = f2tf(pw1.w);
            *reinterpret_cast<uint4*>(Ws + (r0 + 64) * 20 + kq0) = u;
        }
        __syncthreads();

        if (kt + 16 < K) {   // prefetch next tile while computing
            int kn = kt + 16;
            pa0 = *reinterpret_cast<const float4*>(A  + (size_t)(m0 + r0)      * K + kn + kq0);
            pa1 = *reinterpret_cast<const float4*>(A  + (size_t)(m0 + r0 + 64) * K + kn + kq0);
            pw0 = *reinterpret_cast<const float4*>(Wd + (size_t)(n0 + r0)      * K + kn + kq0);
            pw1 = *reinterpret_cast<const float4*>(Wd + (size_t)(n0 + r0 + 64) * K + kn + kq0);
        }

#pragma unroll
        for (int kk = 0; kk < 16; kk += 8) {
            unsigned af[4][4], bf[4][2];
#pragma unroll
            for (int mt = 0; mt < 4; ++mt) {
                const unsigned* p = As + (wm + mt * 16 + (lane >> 2)) * 20 + kk + (lane & 3);
                af[mt][0] = p[0];
                af[mt][1] = p[8 * 20];
                af[mt][2] = p[4];
                af[mt][3] = p[8 * 20 + 4];
            }
#pragma unroll
            for (int nt = 0; nt < 4; ++nt) {
                const unsigned* p = Ws + (wn + nt * 8 + (lane >> 2)) * 20 + kk + (lane & 3);
                bf[nt][0] = p[0];
                bf[nt][1] = p[4];
            }
#pragma unroll
            for (int mt = 0; mt < 4; ++mt)
#pragma unroll
                for (int nt = 0; nt < 4; ++nt)
                    mma_tf32(acc[mt][nt], af[mt][0], af[mt][1], af[mt][2], af[mt][3],
                             bf[nt][0], bf[nt][1]);
        }
        __syncthreads();
    }

    // epilogue: bias + scatter to g_xg
#pragma unroll
    for (int mt = 0; mt < 4; ++mt) {
        int mrow0 = m0 + wm + mt * 16 + (lane >> 2);
#pragma unroll
        for (int nt = 0; nt < 4; ++nt) {
            int n = n0 + wn + nt * 8 + (lane & 3) * 2;
            float bv0 = bd[n], bv1 = bd[n + 1];
#pragma unroll
            for (int h = 0; h < 2; ++h) {
                int m  = mrow0 + h * 8;
                int t  = m & (Tn - 1);
                int bb = m >> 9;
                float* cp = g_xg + (((size_t)d * Tn + t) * Bsz + bb) * G4 + n;
                *reinterpret_cast<float2*>(cp) =
                    make_float2(acc[mt][nt][h * 2 + 0] + bv0,
                                acc[mt][nt][h * 2 + 1] + bv1);
            }
        }
    }
}

// ---------------- persistent bidirectional LSTM recurrence (tf32 MMA) -----
// NB=64 blocks: (d = bx>>5, j-slice j0 = (bx&31)*16 -> 64 gate rows).
// Warp = (qh: gate-q half, kc: K chunk of 128). wa = 16ks x 2q x 4 = 128 regs,
// acc = 2x4x4 = 32 regs (low pressure, no spill). 4-way K-split partials in
// smem; hs stride 516 (conflict-free fragment LDS). ONE grid_sync per step.
#define REC_SMEM ((32 * 516 + 4 * 64 * 34) * 4)
extern __shared__ unsigned smr[];

__global__ void __launch_bounds__(256, 1)
rec_kernel(const float* __restrict__ whh,      // [2][4H][H]
           const int*   __restrict__ lengths,
           int outSel) {
    unsigned* hs   = smr;                          // [32 b][516] tf32 bits
    float*    part = (float*)(smr + 32 * 516);     // [4 kc][64 g][34 b]
    float* out = outSel ? g_out1 : g_out0;

    const int tid  = threadIdx.x;
    const int lane = tid & 31;
    const int wid  = tid >> 5;
    const int qh   = wid & 1;             // gate-q half: q = qh*2 + qq
    const int kc   = wid >> 1;            // K chunk (0..3), 128 k each
    const int bx   = blockIdx.x;
    const int d    = bx >> 5;
    const int j0   = (bx & 31) << 4;

    // stationary W fragments (A side): wa[ks][qq][0..3]
    unsigned wa[16][2][4];
    {
        const float* wdb = whh + (size_t)d * G4 * Hn;
#pragma unroll
        for (int ks = 0; ks < 16; ++ks)
#pragma unroll
            for (int qq = 0; qq < 2; ++qq) {
                const int q = qh * 2 + qq;
                const float* wp = wdb + (size_t)(q * Hn + j0 + (lane >> 2)) * Hn
                                  + kc * 128 + ks * 8 + (lane & 3);
                wa[ks][qq][0] = f2tf(wp[0]);
                wa[ks][qq][1] = f2tf(wp[8 * (size_t)Hn]);
                wa[ks][qq][2] = f2tf(wp[4]);
                wa[ks][qq][3] = f2tf(wp[8 * (size_t)Hn + 4]);
            }
    }

    // phase-2 identity: jj-major lanes -> coalesced xg/out accesses
    const int jj  = tid & 15;
    const int b2a = tid >> 4;             // 0..15 ; second batch = b2a+16
    const int lenA = lengths[b2a];
    const int lenB = lengths[b2a + 16];
    const int hidxA = (d * Bsz + b2a) * Hn + j0 + jj;
    const int hidxB = hidxA + 16 * Hn;
    float cA = 0.f, cB = 0.f;
    unsigned hbA = 0u, hbB = 0u;
    g_h[0][hidxA] = 0u;
    g_h[0][hidxB] = 0u;

    grid_sync();   // h buffer 0 zeroed everywhere

    for (int s = 0; s < Tn; ++s) {
        const int pr = s & 1, pw_ = pr ^ 1;
        const bool actA = s < lenA, actB = s < lenB;
        const int tA = d ? (lenA - 1 - s) : s;
        const int tB = d ? (lenB - 1 - s) : s;

        // prefetch xg (64B-contiguous per (b,q))
        float xvA[4], xvB[4];
        if (actA) {
            const float* xr = g_xg + (((size_t)d * Tn + tA) * Bsz + b2a) * G4 + j0 + jj;
            xvA[0] = xr[0]; xvA[1] = xr[Hn]; xvA[2] = xr[2 * Hn]; xvA[3] = xr[3 * Hn];
        }
        if (actB) {
            const float* xr = g_xg + (((size_t)d * Tn + tB) * Bsz + b2a + 16) * G4 + j0 + jj;
            xvB[0] = xr[0]; xvB[1] = xr[Hn]; xvB[2] = xr[2 * Hn]; xvB[3] = xr[3 * Hn];
        }

        // stage h (own dir, 64KB) into smem [b][k]
        {
            const unsigned* hsrc = g_h[pr] + d * Bsz * Hn;
#pragma unroll
            for (int i = 0; i < 16; ++i) {
                int f = tid + i * 256;
                int r = f >> 7, kq = (f & 127) << 2;
                *reinterpret_cast<uint4*>(hs + r * 516 + kq) =
                    *reinterpret_cast<const uint4*>(hsrc + r * Hn + kq);
            }
        }
        __syncthreads();

        float acc[2][4][4];
#pragma unroll
        for (int qq = 0; qq < 2; ++qq)
#pragma unroll
            for (int nt = 0; nt < 4; ++nt)
#pragma unroll
                for (int i = 0; i < 4; ++i) acc[qq][nt][i] = 0.f;

#pragma unroll
        for (int ks = 0; ks < 16; ++ks) {
#pragma unroll
            for (int nt = 0; nt < 4; ++nt) {
                const unsigned* hp = hs + (nt * 8 + (lane >> 2)) * 516
                                     + kc * 128 + ks * 8 + (lane & 3);
                unsigned b0 = hp[0], b1 = hp[4];
                mma_tf32(acc[0][nt], wa[ks][0][0], wa[ks][0][1],
                         wa[ks][0][2], wa[ks][0][3], b0, b1);
                mma_tf32(acc[1][nt], wa[ks][1][0], wa[ks][1][1],
                         wa[ks][1][2], wa[ks][1][3], b0, b1);
            }
        }

        // write K-chunk partials: part[kc][gate row][batch]
#pragma unroll
        for (int qq = 0; qq < 2; ++qq) {
            const int q = qh * 2 + qq;
#pragma unroll
            for (int nt = 0; nt < 4; ++nt) {
                float* pp = part + ((size_t)kc * 64 + q * 16 + (lane >> 2)) * 34
                            + nt * 8 + ((lane & 3) << 1);
                *reinterpret_cast<float2*>(pp) =
                    make_float2(acc[qq][nt][0], acc[qq][nt][1]);
                *reinterpret_cast<float2*>(pp + 8 * 34) =
                    make_float2(acc[qq][nt][2], acc[qq][nt][3]);
            }
        }
        __syncthreads();

        // phase 2: reduce 4 K-chunk partials + gates (2 batches per thread)
        if (actA) {
            float gv[4];
#pragma unroll
            for (int q = 0; q < 4; ++q) {
                float v = xvA[q];
#pragma unroll
                for (int k2 = 0; k2 < 4; ++k2)
                    v += part[(k2 * 64 + q * 16 + jj) * 34 + b2a];
                gv[q] = v;
            }
            float ig = 1.f / (1.f + __expf(-gv[0]));
            float fg = 1.f / (1.f + __expf(-gv[1]));
            float gg = tanhf(gv[2]);
            float og = 1.f / (1.f + __expf(-gv[3]));
            cA = fg * cA + ig * gg;
            float hn = og * tanhf(cA);
            hbA = f2tf(hn);
            out[((size_t)b2a * Tn + tA) * (2 * Hn) + d * Hn + j0 + jj] = hn;
        }
        if (actB) {
            float gv[4];
#pragma unroll
            for (int q = 0; q < 4; ++q) {
                float v = xvB[q];
#pragma unroll
                for (int k2 = 0; k2 < 4; ++k2)
                    v += part[(k2 * 64 + q * 16 + jj) * 34 + b2a + 16];
                gv[q] = v;
            }
            float ig = 1.f / (1.f + __expf(-gv[0]));
            float fg = 1.f / (1.f + __expf(-gv[1]));
            float gg = tanhf(gv[2]);
            float og = 1.f / (1.f + __expf(-gv[3]));
            cB = fg * cB + ig * gg;
            float hn = og * tanhf(cB);
            hbB = f2tf(hn);
            out[((size_t)(b2a + 16) * Tn + tB) * (2 * Hn) + d * Hn + j0 + jj] = hn;
        }
        g_h[pw_][hidxA] = hbA;   // frozen h re-written when inactive
        g_h[pw_][hidxB] = hbB;

        grid_sync();
    }
}

// ---------------- mean pooling over valid length --------------------------
__global__ void pool_kernel(const int* __restrict__ lengths,
                            float* __restrict__ out) {
    const int c = blockIdx.x * 256 + threadIdx.x;
    const int b = blockIdx.y;
    const float* p = g_out1 + (size_t)b * Tn * (2 * Hn) + c;
    float s = 0.f;
    for (int t = 0; t < Tn; ++t) s += p[(size_t)t * (2 * Hn)];
    out[b * (2 * Hn) + c] = s / (float)lengths[b];
}

// ---------------- launch ---------------------------------------------------
extern "C" void kernel_launch(void* const* d_in, const int* in_sizes, int n_in,
                              void* d_out, int out_size) {
    const float* feats = (const float*)d_in[0];
    const int*   lens  = (const int*)  d_in[1];
    const float* encW  = (const float*)d_in[2];
    const float* encb  = (const float*)d_in[3];
    const float* wih0  = (const float*)d_in[4];
    const float* whh0  = (const float*)d_in[5];
    const float* b0    = (const float*)d_in[6];
    const float* wih1  = (const float*)d_in[7];
    const float* whh1  = (const float*)d_in[8];
    const float* b1    = (const float*)d_in[9];
    float* out = (float*)d_out;

    // opt-in to >48KB dynamic smem (attribute set, not an allocation)
    cudaFuncSetAttribute(rec_kernel,
                         cudaFuncAttributeMaxDynamicSharedMemorySize, REC_SMEM);

    zero_kernel<<<2048, 256>>>();
    enc_kernel<<<Bsz * Tn, 256>>>(feats, encW, encb);

    // layer 0: project (K=256) then scan
    {
        dim3 grid(16, 128, 2);
        proj_gemm<<<grid, 256>>>(0, DENC, wih0, b0);
        rec_kernel<<<NB, 256, REC_SMEM>>>(whh0, lens, 0);
    }
    // layer 1: project (K=1024) then scan
    {
        dim3 grid(16, 128, 2);
        proj_gemm<<<grid, 256>>>(1, 2 * Hn, wih1, b1);
        rec_kernel<<<NB, 256, REC_SMEM>>>(whh1, lens, 1);
    }

    dim3 pg(4, Bsz);
    pool_kernel<<<pg, 256>>>(lens, out);
}

// round 9
// speedup vs baseline: 1.2782x; 1.2311x over previous
#include <cuda_runtime.h>
#include <math.h>

// Problem constants
#define Bsz   32
#define Tn    512
#define Jn    25
#define DENC  256
#define Hn    512
#define G4    2048      // 4*H
#define NB    128       // persistent recurrence grid (co-resident)

// ---------------- scratch (device globals; no allocations) ----------------
__device__ float    g_enc [Bsz * Tn * DENC];
__device__ float    g_xg  [2L * Tn * Bsz * G4];           // [d][t][b][4H]
__device__ float    g_out0[Bsz * Tn * 2 * Hn];            // [b][t][2H]
__device__ float    g_out1[Bsz * Tn * 2 * Hn];
__device__ unsigned g_h   [2][2 * Bsz * Hn];              // tf32 bits, double-buffered
__device__ unsigned g_bar_cnt;
__device__ unsigned g_bar_gen;

// ---------------- helpers --------------------------------------------------
__device__ __forceinline__ unsigned f2tf(float x) {
    unsigned u;
    asm("cvt.rna.tf32.f32 %0, %1;" : "=r"(u) : "f"(x));
    return u;
}

__device__ __forceinline__ void mma_tf32(float* c,
                                         unsigned a0, unsigned a1,
                                         unsigned a2, unsigned a3,
                                         unsigned b0, unsigned b1) {
    asm("mma.sync.aligned.m16n8k8.row.col.f32.tf32.tf32.f32 "
        "{%0,%1,%2,%3}, {%4,%5,%6,%7}, {%8,%9}, {%0,%1,%2,%3};"
        : "+f"(c[0]), "+f"(c[1]), "+f"(c[2]), "+f"(c[3])
        : "r"(a0), "r"(a1), "r"(a2), "r"(a3), "r"(b0), "r"(b1));
}

// ---------------- grid-wide barrier (all NB blocks resident) --------------
__device__ __forceinline__ void grid_sync() {
    __threadfence();
    __syncthreads();
    if (threadIdx.x == 0) {
        volatile unsigned* vg = &g_bar_gen;
        unsigned gen = *vg;
        if (atomicAdd(&g_bar_cnt, 1u) == NB - 1) {
            g_bar_cnt = 0;
            __threadfence();
            *vg = gen + 1;
        } else {
            while (*vg == gen) { __nanosleep(32); }
        }
    }
    __syncthreads();
    __threadfence();
}

// ---------------- zero the output buffers ---------------------------------
__global__ void zero_kernel() {
    const int n4 = (Bsz * Tn * 2 * Hn) / 4;
    float4 z = make_float4(0.f, 0.f, 0.f, 0.f);
    for (int i = blockIdx.x * blockDim.x + threadIdx.x; i < n4;
         i += gridDim.x * blockDim.x) {
        reinterpret_cast<float4*>(g_out0)[i] = z;
        reinterpret_cast<float4*>(g_out1)[i] = z;
    }
}

// ---------------- encoder: relu(masked_xy @ W^T + b) ----------------------
__global__ void enc_kernel(const float* __restrict__ feats,
                           const float* __restrict__ W,
                           const float* __restrict__ bias) {
    __shared__ float xs[2 * Jn];
    const int bt  = blockIdx.x;
    const int tid = threadIdx.x;
    const float* f = feats + (size_t)bt * (Jn * 3);
    if (tid < Jn) {
        float c = (f[tid * 3 + 2] > 0.1f) ? 1.f : 0.f;
        xs[tid * 2 + 0] = f[tid * 3 + 0] * c;
        xs[tid * 2 + 1] = f[tid * 3 + 1] * c;
    }
    __syncthreads();
    const float* w = W + tid * (2 * Jn);
    float s = bias[tid];
#pragma unroll
    for (int k = 0; k < 2 * Jn; ++k) s += xs[k] * w[k];
    g_enc[(size_t)bt * DENC + tid] = fmaxf(s, 0.f);
}

// ---------------- input projection GEMM (tf32, double-buffered) -----------
// out_xg[d][t][b][g] = A[m=b*T+t,:K] . W[d][g,:K] + bias[d][g]
// block 128x128, 8 warps (2m x 4n), k-tile 16, ping-pong smem (1 sync/tile)
__global__ void __launch_bounds__(256)
proj_gemm(int srcSel, int K, const float* __restrict__ W,
          const float* __restrict__ bias) {
    const float* A  = srcSel ? g_out0 : g_enc;
    const int d  = blockIdx.z;
    const float* Wd = W + (size_t)d * G4 * K;
    const float* bd = bias + d * G4;
    const int n0 = blockIdx.x * 128;
    const int m0 = blockIdx.y * 128;

    __shared__ unsigned As[2][128 * 20];   // [m][k], stride 20 (conflict-free)
    __shared__ unsigned Ws[2][128 * 20];   // [n][k]

    const int tid  = threadIdx.x;
    const int lane = tid & 31;
    const int wid  = tid >> 5;
    const int wm   = (wid >> 2) * 64;
    const int wn   = (wid & 3) * 32;

    float acc[4][4][4];
#pragma unroll
    for (int mt = 0; mt < 4; ++mt)
#pragma unroll
        for (int nt = 0; nt < 4; ++nt)
#pragma unroll
            for (int i = 0; i < 4; ++i) acc[mt][nt][i] = 0.f;

    const int r0  = tid >> 2;
    const int kq0 = (tid & 3) << 2;

    float4 pa0, pa1, pw0, pw1;
    pa0 = *reinterpret_cast<const float4*>(A  + (size_t)(m0 + r0)      * K + kq0);
    pa1 = *reinterpret_cast<const float4*>(A  + (size_t)(m0 + r0 + 64) * K + kq0);
    pw0 = *reinterpret_cast<const float4*>(Wd + (size_t)(n0 + r0)      * K + kq0);
    pw1 = *reinterpret_cast<const float4*>(Wd + (size_t)(n0 + r0 + 64) * K + kq0);

    const int KT = K >> 4;
    for (int kt = 0; kt < KT; ++kt) {
        const int p = kt & 1;
        {
            uint4 u;
            u.x = f2tf(pa0.x); u.y = f2tf(pa0.y); u.z = f2tf(pa0.z); u.w = f2tf(pa0.w);
            *reinterpret_cast<uint4*>(As[p] + r0 * 20 + kq0) = u;
            u.x = f2tf(pa1.x); u.y = f2tf(pa1.y); u.z = f2tf(pa1.z); u.w = f2tf(pa1.w);
            *reinterpret_cast<uint4*>(As[p] + (r0 + 64) * 20 + kq0) = u;
            u.x = f2tf(pw0.x); u.y = f2tf(pw0.y); u.z = f2tf(pw0.z); u.w = f2tf(pw0.w);
            *reinterpret_cast<uint4*>(Ws[p] + r0 * 20 + kq0) = u;
            u.x = f2tf(pw1.x); u.y = f2tf(pw1.y); u.z = f2tf(pw1.z); u.w = f2tf(pw1.w);
            *reinterpret_cast<uint4*>(Ws[p] + (r0 + 64) * 20 + kq0) = u;
        }
        __syncthreads();     // single barrier per tile (ping-pong buffers)

        if (kt + 1 < KT) {   // prefetch next tile while computing
            int kn = (kt + 1) << 4;
            pa0 = *reinterpret_cast<const float4*>(A  + (size_t)(m0 + r0)      * K + kn + kq0);
            pa1 = *reinterpret_cast<const float4*>(A  + (size_t)(m0 + r0 + 64) * K + kn + kq0);
            pw0 = *reinterpret_cast<const float4*>(Wd + (size_t)(n0 + r0)      * K + kn + kq0);
            pw1 = *reinterpret_cast<const float4*>(Wd + (size_t)(n0 + r0 + 64) * K + kn + kq0);
        }

        const unsigned* Ab = As[p];
        const unsigned* Bb = Ws[p];
#pragma unroll
        for (int kk = 0; kk < 16; kk += 8) {
            unsigned af[4][4], bf[4][2];
#pragma unroll
            for (int mt = 0; mt < 4; ++mt) {
                const unsigned* pp = Ab + (wm + mt * 16 + (lane >> 2)) * 20 + kk + (lane & 3);
                af[mt][0] = pp[0];
                af[mt][1] = pp[8 * 20];
                af[mt][2] = pp[4];
                af[mt][3] = pp[8 * 20 + 4];
            }
#pragma unroll
            for (int nt = 0; nt < 4; ++nt) {
                const unsigned* pp = Bb + (wn + nt * 8 + (lane >> 2)) * 20 + kk + (lane & 3);
                bf[nt][0] = pp[0];
                bf[nt][1] = pp[4];
            }
#pragma unroll
            for (int mt = 0; mt < 4; ++mt)
#pragma unroll
                for (int nt = 0; nt < 4; ++nt)
                    mma_tf32(acc[mt][nt], af[mt][0], af[mt][1], af[mt][2], af[mt][3],
                             bf[nt][0], bf[nt][1]);
        }
    }

    // epilogue: bias + scatter to g_xg
#pragma unroll
    for (int mt = 0; mt < 4; ++mt) {
        int mrow0 = m0 + wm + mt * 16 + (lane >> 2);
#pragma unroll
        for (int nt = 0; nt < 4; ++nt) {
            int n = n0 + wn + nt * 8 + (lane & 3) * 2;
            float bv0 = bd[n], bv1 = bd[n + 1];
#pragma unroll
            for (int h = 0; h < 2; ++h) {
                int m  = mrow0 + h * 8;
                int t  = m & (Tn - 1);
                int bb = m >> 9;
                float* cp = g_xg + (((size_t)d * Tn + t) * Bsz + bb) * G4 + n;
                *reinterpret_cast<float2*>(cp) =
                    make_float2(acc[mt][nt][h * 2 + 0] + bv0,
                                acc[mt][nt][h * 2 + 1] + bv1);
            }
        }
    }
}

// ---------------- persistent bidirectional LSTM recurrence (tf32 MMA) -----
// R5 structure (NB=128, W stationary, 1 grid_sync/step) with two fixes:
//  - part transposed to [batch][kc*32 + q*8 + j], stride 136 (== 8 mod 32)
//    -> phase-2 smem reads are bank-conflict-free (were 32-way in R5)
//  - phase-2 threads jj-major -> xg/out/g_h accesses 32B-coalesced
#define REC_SMEM ((32 * 516 + 32 * 136) * 4)
extern __shared__ unsigned smr[];

__global__ void __launch_bounds__(256, 1)
rec_kernel(const float* __restrict__ whh,      // [2][4H][H]
           const int*   __restrict__ lengths,
           int outSel) {
    unsigned* hs   = smr;                          // [32 b][516] tf32 bits
    float*    part = (float*)(smr + 32 * 516);     // [32 b][136]
    float* out = outSel ? g_out1 : g_out0;
    const float* xg = g_xg;

    const int tid  = threadIdx.x;
    const int lane = tid & 31;
    const int wid  = tid >> 5;
    const int bx   = blockIdx.x;
    const int d    = bx >> 6;
    const int j0   = (bx & 63) << 3;
    const int mb   = wid & 1;             // batch half
    const int kc   = wid >> 1;            // K chunk (0..3), 128 k each

    // stationary W fragments (B side): b0,b1 per (ks, nt=q)
    unsigned wb0[16][4], wb1[16][4];
    {
        const float* wdb = whh + (size_t)d * G4 * Hn;
#pragma unroll
        for (int ks = 0; ks < 16; ++ks)
#pragma unroll
            for (int nt = 0; nt < 4; ++nt) {
                const float* wp = wdb + (size_t)(nt * Hn + j0 + (lane >> 2)) * Hn
                                  + kc * 128 + ks * 8 + (lane & 3);
                wb0[ks][nt] = f2tf(wp[0]);
                wb1[ks][nt] = f2tf(wp[4]);
            }
    }

    // phase-2 identity: jj-major -> coalesced gmem
    const int jj = tid & 7;
    const int b2 = tid >> 3;              // 0..31
    const int len = lengths[b2];
    const int hidx = (d * Bsz + b2) * Hn + j0 + jj;
    float c_reg = 0.f;
    unsigned h_bits = 0u;
    g_h[0][hidx] = 0u;

    grid_sync();   // h buffer 0 zeroed everywhere

    for (int s = 0; s < Tn; ++s) {
        const int pr = s & 1, pw_ = pr ^ 1;
        const bool act = s < len;
        const int t = d ? (len - 1 - s) : s;

        // prefetch xg (32B-coalesced per (b,q) group)
        float xv0 = 0.f, xv1 = 0.f, xv2 = 0.f, xv3 = 0.f;
        if (act) {
            const float* xr = xg + (((size_t)d * Tn + t) * Bsz + b2) * G4 + j0 + jj;
            xv0 = xr[0];
            xv1 = xr[Hn];
            xv2 = xr[2 * Hn];
            xv3 = xr[3 * Hn];
        }

        // stage h (own dir, 64KB) into smem [b][k]
        {
            const unsigned* hsrc = g_h[pr] + d * Bsz * Hn;
#pragma unroll
            for (int i = 0; i < 16; ++i) {
                int f = tid + i * 256;
                int r = f >> 7, kq = (f & 127) << 2;
                *reinterpret_cast<uint4*>(hs + r * 516 + kq) =
                    *reinterpret_cast<const uint4*>(hsrc + r * Hn + kq);
            }
        }
        __syncthreads();

        float acc[4][4];
#pragma unroll
        for (int nt = 0; nt < 4; ++nt)
#pragma unroll
            for (int i = 0; i < 4; ++i) acc[nt][i] = 0.f;

#pragma unroll
        for (int ks = 0; ks < 16; ++ks) {
            const unsigned* hp = hs + (mb * 16 + (lane >> 2)) * 516
                                 + kc * 128 + ks * 8 + (lane & 3);
            unsigned a0 = hp[0];
            unsigned a2 = hp[4];
            unsigned a1 = hp[8 * 516];
            unsigned a3 = hp[8 * 516 + 4];
#pragma unroll
            for (int nt = 0; nt < 4; ++nt)
                mma_tf32(acc[nt], a0, a1, a2, a3, wb0[ks][nt], wb1[ks][nt]);
        }

        // write K-chunk partials: part[batch][kc*32 + q*8 + jcol]
        {
            const int b_lo = mb * 16 + (lane >> 2);
            const int col  = kc * 32 + ((lane & 3) << 1);
#pragma unroll
            for (int nt = 0; nt < 4; ++nt) {
                float* pp = part + b_lo * 136 + col + nt * 8;
                *reinterpret_cast<float2*>(pp) =
                    make_float2(acc[nt][0], acc[nt][1]);
                *reinterpret_cast<float2*>(pp + 8 * 136) =
                    make_float2(acc[nt][2], acc[nt][3]);
            }
        }
        __syncthreads();

        // phase 2: reduce 4 K-chunk partials + gates (conflict-free reads)
        if (act) {
            const float* pb = part + b2 * 136 + jj;
            float gv[4];
#pragma unroll
            for (int q = 0; q < 4; ++q) {
                float v = (q == 0) ? xv0 : (q == 1) ? xv1 : (q == 2) ? xv2 : xv3;
#pragma unroll
                for (int k2 = 0; k2 < 4; ++k2)
                    v += pb[k2 * 32 + q * 8];
                gv[q] = v;
            }
            float ig = 1.f / (1.f + __expf(-gv[0]));
            float fg = 1.f / (1.f + __expf(-gv[1]));
            float gg = tanhf(gv[2]);
            float og = 1.f / (1.f + __expf(-gv[3]));
            c_reg = fg * c_reg + ig * gg;
            float hn = og * tanhf(c_reg);
            h_bits = f2tf(hn);
            out[((size_t)b2 * Tn + t) * (2 * Hn) + d * Hn + j0 + jj] = hn;
        }
        g_h[pw_][hidx] = h_bits;   // frozen h re-written when inactive

        grid_sync();
    }
}

// ---------------- mean pooling over valid length --------------------------
__global__ void pool_kernel(const int* __restrict__ lengths,
                            float* __restrict__ out) {
    const int c = blockIdx.x * 256 + threadIdx.x;
    const int b = blockIdx.y;
    const float* p = g_out1 + (size_t)b * Tn * (2 * Hn) + c;
    float s = 0.f;
    for (int t = 0; t < Tn; ++t) s += p[(size_t)t * (2 * Hn)];
    out[b * (2 * Hn) + c] = s / (float)lengths[b];
}

// ---------------- launch ---------------------------------------------------
extern "C" void kernel_launch(void* const* d_in, const int* in_sizes, int n_in,
                              void* d_out, int out_size) {
    const float* feats = (const float*)d_in[0];
    const int*   lens  = (const int*)  d_in[1];
    const float* encW  = (const float*)d_in[2];
    const float* encb  = (const float*)d_in[3];
    const float* wih0  = (const float*)d_in[4];
    const float* whh0  = (const float*)d_in[5];
    const float* b0    = (const float*)d_in[6];
    const float* wih1  = (const float*)d_in[7];
    const float* whh1  = (const float*)d_in[8];
    const float* b1    = (const float*)d_in[9];
    float* out = (float*)d_out;

    // opt-in to >48KB dynamic smem (attribute set, not an allocation)
    cudaFuncSetAttribute(rec_kernel,
                         cudaFuncAttributeMaxDynamicSharedMemorySize, REC_SMEM);

    zero_kernel<<<2048, 256>>>();
    enc_kernel<<<Bsz * Tn, 256>>>(feats, encW, encb);

    // layer 0: project (K=256) then scan
    {
        dim3 grid(16, 128, 2);
        proj_gemm<<<grid, 256>>>(0, DENC, wih0, b0);
        rec_kernel<<<NB, 256, REC_SMEM>>>(whh0, lens, 0);
    }
    // layer 1: project (K=1024) then scan
    {
        dim3 grid(16, 128, 2);
        proj_gemm<<<grid, 256>>>(1, 2 * Hn, wih1, b1);
        rec_kernel<<<NB, 256, REC_SMEM>>>(whh1, lens, 1);
    }

    dim3 pg(4, Bsz);
    pool_kernel<<<pg, 256>>>(lens, out);
}